// round 14
// baseline (speedup 1.0000x reference)
#include <cuda_runtime.h>
#include <cuda_fp16.h>
#include <cstdint>

#define N_NODES 50000
#define N_EDGES 800000
#define NUM_GRAPHS 512
#define NBLK 49  // ceil(50000/1024)
#define NCHUNK 4

// ---------------- scratch (no allocations allowed) ----------------
__device__ __align__(16) __half g_h0[N_NODES * 64];
__device__ __align__(16) __half g_h1[N_NODES * 64];
__device__ __align__(16) __half g_h2[N_NODES * 128];
__device__ __align__(16) float  g_agg[N_NODES * 128];
__device__ __align__(16) float  g_pool[NUM_GRAPHS * 128];
__device__ int   g_cnt[NUM_GRAPHS];
__device__ int   g_src[N_EDGES];
__device__ int   g_dst[N_EDGES];
__device__ int   g_batch[N_NODES];
__device__ int   g_deg[N_NODES];
__device__ int   g_off[N_NODES + 1];
__device__ int   g_fill[N_NODES];
__device__ int   g_csr[N_EDGES];
__device__ int   g_bsum[NBLK];

__device__ __forceinline__ __half* hbuf_ptr(int id) {
    switch (id) {
        case 0: return g_h0;
        case 1: return g_h1;
        default: return g_h2;
    }
}

// ---------------- converts (dtype-detecting) fused with hist/count ----------------
__global__ void zero_deg_kernel() {
    int i = blockIdx.x * blockDim.x + threadIdx.x;
    if (i < N_NODES) g_deg[i] = 0;
}

__global__ void convert_edges_hist_kernel(const void* __restrict__ ei_raw, int E) {
    const int* w = (const int*)ei_raw;
    bool is64 = true;
#pragma unroll
    for (int j = 1; j < 32; j += 2) is64 &= (w[j] == 0);
    int i = blockIdx.x * blockDim.x + threadIdx.x;
    if (i >= E) return;
    int s, d;
    if (is64) {
        const long long* e64 = (const long long*)ei_raw;
        s = (int)e64[i];
        d = (int)e64[E + i];
    } else {
        s = w[i];
        d = w[E + i];
    }
    g_src[i] = s;
    g_dst[i] = d;
    atomicAdd(&g_deg[d], 1);
}

__global__ void zero_pool_kernel() {
    int i = blockIdx.x * blockDim.x + threadIdx.x;
    if (i < NUM_GRAPHS * 128) g_pool[i] = 0.f;
    if (i < NUM_GRAPHS) g_cnt[i] = 0;
}

__global__ void convert_batch_count_kernel(const void* __restrict__ b_raw, int N) {
    const int* w = (const int*)b_raw;
    bool is64 = true;
#pragma unroll
    for (int j = 0; j < 32; ++j) {
        int idx = N - 32 + j;
        if (idx & 1) is64 &= (w[idx] == 0);
    }
    int i = blockIdx.x * blockDim.x + threadIdx.x;
    if (i >= N) return;
    int b = is64 ? (int)((const long long*)b_raw)[i] : w[i];
    g_batch[i] = b;
    atomicAdd(&g_cnt[b], 1);
}

// ---------------- CSR scan + fill ----------------
__global__ void scan1_kernel() {
    __shared__ int wsum[32];
    int t = threadIdx.x;
    int i = blockIdx.x * 1024 + t;
    int v = (i < N_NODES) ? g_deg[i] : 0;
    int lane = t & 31, wid = t >> 5;
    int x = v;
#pragma unroll
    for (int d = 1; d < 32; d <<= 1) {
        int y = __shfl_up_sync(0xFFFFFFFFu, x, d);
        if (lane >= d) x += y;
    }
    if (lane == 31) wsum[wid] = x;
    __syncthreads();
    if (wid == 0) {
        int w = wsum[lane];
#pragma unroll
        for (int d = 1; d < 32; d <<= 1) {
            int y = __shfl_up_sync(0xFFFFFFFFu, w, d);
            if (lane >= d) w += y;
        }
        wsum[lane] = w;
    }
    __syncthreads();
    int incl = x + ((wid > 0) ? wsum[wid - 1] : 0);
    if (i < N_NODES) g_off[i] = incl - v;
    if (t == 1023) g_bsum[blockIdx.x] = incl;
}

__global__ void scan23_kernel() {
    __shared__ int s[NBLK];
    __shared__ int pre;
    int t = threadIdx.x;
    if (t < NBLK) s[t] = g_bsum[t];
    __syncthreads();
    if (t == 0) {
        int acc = 0;
        for (int j = 0; j < (int)blockIdx.x; ++j) acc += s[j];
        pre = acc;
        if (blockIdx.x == 0) {
            int tot = 0;
            for (int j = 0; j < NBLK; ++j) tot += s[j];
            g_off[N_NODES] = tot;
        }
    }
    __syncthreads();
    int i = blockIdx.x * 1024 + t;
    if (i < N_NODES) {
        int o = g_off[i] + pre;
        g_off[i] = o;
        g_fill[i] = o;
    }
}

__global__ void fill_kernel(int E) {
    int i = blockIdx.x * blockDim.x + threadIdx.x;
    if (i < E) {
        int p = atomicAdd(&g_fill[g_dst[i]], 1);
        g_csr[p] = g_src[i];
    }
}

// ---------------- CSR gather (fp16 h -> fp32 agg) over nodes [n0, n1) ----------------
__device__ __forceinline__ void acc8h(float* acc, uint4 v) {
    const __half2* hp = (const __half2*)&v;
#pragma unroll
    for (int j = 0; j < 4; ++j) {
        float2 f = __half22float2(hp[j]);
        acc[2 * j] += f.x;
        acc[2 * j + 1] += f.y;
    }
}

template <int LANES>   // LANES = dim/8 (8 for 64-dim, 16 for 128-dim)
__global__ void gather_kernel(int hId, int n0, int n1) {
    int gt = blockIdx.x * blockDim.x + threadIdx.x;
    int gid = n0 + gt / LANES;
    int lane = gt & (LANES - 1);
    if (gid >= n1) return;
    const uint4* __restrict__ h = (const uint4*)hbuf_ptr(hId);  // row = LANES uint4
    const int* __restrict__ csr = g_csr;
    int e = g_off[gid], end = g_off[gid + 1];
    float acc[8] = {0.f, 0.f, 0.f, 0.f, 0.f, 0.f, 0.f, 0.f};
    for (; e + 3 < end; e += 4) {
        int s0 = csr[e], s1 = csr[e + 1], s2 = csr[e + 2], s3 = csr[e + 3];
        uint4 v0 = __ldg(&h[(size_t)s0 * LANES + lane]);
        uint4 v1 = __ldg(&h[(size_t)s1 * LANES + lane]);
        uint4 v2 = __ldg(&h[(size_t)s2 * LANES + lane]);
        uint4 v3 = __ldg(&h[(size_t)s3 * LANES + lane]);
        acc8h(acc, v0); acc8h(acc, v1); acc8h(acc, v2); acc8h(acc, v3);
    }
    for (; e < end; ++e) {
        uint4 v0 = __ldg(&h[(size_t)csr[e] * LANES + lane]);
        acc8h(acc, v0);
    }
    float4* ap = (float4*)(g_agg + ((size_t)gid * LANES + lane) * 8);
    ap[0] = make_float4(acc[0], acc[1], acc[2], acc[3]);
    ap[1] = make_float4(acc[4], acc[5], acc[6], acc[7]);
}

// ---------------- tf32 mma.sync GEMM (NB=64 tile, occupancy 3, row-chunked) ----------------
__device__ __forceinline__ float to_tf32(float x) {
    float y;
    asm("cvt.rna.tf32.f32 %0, %1;" : "=f"(y) : "f"(x));
    return y;
}
__device__ __forceinline__ void mma1688(float* d, const uint32_t* a, const uint32_t* b) {
    asm volatile(
        "mma.sync.aligned.m16n8k8.row.col.f32.tf32.tf32.f32 "
        "{%0,%1,%2,%3}, {%4,%5,%6,%7}, {%8,%9}, {%0,%1,%2,%3};\n"
        : "+f"(d[0]), "+f"(d[1]), "+f"(d[2]), "+f"(d[3])
        : "r"(a[0]), "r"(a[1]), "r"(a[2]), "r"(a[3]), "r"(b[0]), "r"(b[1]));
}

#define KC 64
#define LDA 68
#define NB 64
#define NI 4
#define LDB 72
#define GEMM_SMEM ((128 * LDA + KC * LDB) * 4)

// pass0: A = (a32 != nullptr ? a32 : g_agg)  (fp32, K-major).
// pass1 (if Kb>0): A = hbuf[bHalfId] (fp16).
// out: poolMode ? reduce relu into g_pool : store fp16 into hbuf[outId].
__global__ void __launch_bounds__(256, 3)
gemm_mma_kernel(const float* __restrict__ a32, int bHalfId,
                const float* __restrict__ Wa, const float* __restrict__ Wb,
                const float* __restrict__ bias, int outId,
                int rowOff, int M, int Ka, int Kb, int Nfull, int doRelu, int poolMode) {
    extern __shared__ float sm[];
    float* sA = sm;
    float* sB = sm + 128 * LDA;

    int tid = threadIdx.x;
    int wid = tid >> 5, lane = tid & 31;
    int tig = lane & 3, grp = lane >> 2;
    int warp_m = wid & 3, warp_n = wid >> 2;
    int rowbase = rowOff + blockIdx.x * 128;
    int colbase = blockIdx.y * NB;
    int valid = M - rowbase; if (valid > 128) valid = 128;

    const float* A0 = (a32 != nullptr) ? a32 : g_agg;   // device-side symbol!

    float acc[2][NI][4];
#pragma unroll
    for (int mi = 0; mi < 2; ++mi)
#pragma unroll
        for (int ni = 0; ni < NI; ++ni)
#pragma unroll
            for (int j = 0; j < 4; ++j) acc[mi][ni][j] = 0.f;

    const int npass = (Kb > 0) ? 2 : 1;
    for (int pass = 0; pass < npass; ++pass) {
        const float* W = pass ? Wb : Wa;
        const int K = pass ? Kb : Ka;

        for (int kc = 0; kc < K; kc += KC) {
            __syncthreads();
            if (pass == 0) {
                for (int idx = tid; idx < 128 * 16; idx += 256) {
                    int r = idx >> 4, k4 = (idx & 15) * 4;
                    float4 v = make_float4(0.f, 0.f, 0.f, 0.f);
                    if (r < valid)
                        v = *(const float4*)(A0 + (size_t)(rowbase + r) * K + kc + k4);
                    float* p = sA + r * LDA + k4;
                    p[0] = to_tf32(v.x); p[1] = to_tf32(v.y);
                    p[2] = to_tf32(v.z); p[3] = to_tf32(v.w);
                }
            } else {
                const __half* H = hbuf_ptr(bHalfId);
                for (int idx = tid; idx < 128 * 8; idx += 256) {
                    int r = idx >> 3, k8 = (idx & 7) * 8;
                    uint4 v = make_uint4(0, 0, 0, 0);
                    if (r < valid)
                        v = *(const uint4*)(H + (size_t)(rowbase + r) * K + kc + k8);
                    const __half2* hp = (const __half2*)&v;
                    float* p = sA + r * LDA + k8;
#pragma unroll
                    for (int j = 0; j < 4; ++j) {
                        float2 f = __half22float2(hp[j]);
                        p[2 * j] = f.x;         // fp16 -> tf32 is exact
                        p[2 * j + 1] = f.y;
                    }
                }
            }
            for (int idx = tid; idx < KC * (NB / 4); idx += 256) {
                int r = idx >> 4, c4 = (idx & 15) * 4;
                float4 v = *(const float4*)(W + (size_t)(kc + r) * Nfull + colbase + c4);
                float* p = sB + r * LDB + c4;
                p[0] = to_tf32(v.x); p[1] = to_tf32(v.y);
                p[2] = to_tf32(v.z); p[3] = to_tf32(v.w);
            }
            __syncthreads();

#pragma unroll
            for (int k8 = 0; k8 < KC / 8; ++k8) {
                int k0 = k8 * 8;
                uint32_t afr[2][4];
#pragma unroll
                for (int mi = 0; mi < 2; ++mi) {
                    int r0 = warp_m * 32 + mi * 16 + grp;
                    afr[mi][0] = __float_as_uint(sA[r0 * LDA + k0 + tig]);
                    afr[mi][1] = __float_as_uint(sA[(r0 + 8) * LDA + k0 + tig]);
                    afr[mi][2] = __float_as_uint(sA[r0 * LDA + k0 + tig + 4]);
                    afr[mi][3] = __float_as_uint(sA[(r0 + 8) * LDA + k0 + tig + 4]);
                }
                uint32_t bfr[NI][2];
#pragma unroll
                for (int ni = 0; ni < NI; ++ni) {
                    int c = warp_n * (NB / 2) + ni * 8 + grp;
                    bfr[ni][0] = __float_as_uint(sB[(k0 + tig) * LDB + c]);
                    bfr[ni][1] = __float_as_uint(sB[(k0 + tig + 4) * LDB + c]);
                }
#pragma unroll
                for (int mi = 0; mi < 2; ++mi)
#pragma unroll
                    for (int ni = 0; ni < NI; ++ni)
                        mma1688(acc[mi][ni], afr[mi], bfr[ni]);
            }
        }
    }

    if (!poolMode) {
        __half* outp = hbuf_ptr(outId);
#pragma unroll
        for (int mi = 0; mi < 2; ++mi) {
            int r0 = rowbase + warp_m * 32 + mi * 16 + grp;
#pragma unroll
            for (int ni = 0; ni < NI; ++ni) {
                int c = warp_n * (NB / 2) + ni * 8 + tig * 2;
                float b0 = bias[colbase + c], b1 = bias[colbase + c + 1];
                if (r0 < M) {
                    float vx = acc[mi][ni][0] + b0, vy = acc[mi][ni][1] + b1;
                    if (doRelu) { vx = fmaxf(vx, 0.f); vy = fmaxf(vy, 0.f); }
                    *(__half2*)(outp + (size_t)r0 * Nfull + colbase + c) = __floats2half2_rn(vx, vy);
                }
                if (r0 + 8 < M) {
                    float vx = acc[mi][ni][2] + b0, vy = acc[mi][ni][3] + b1;
                    if (doRelu) { vx = fmaxf(vx, 0.f); vy = fmaxf(vy, 0.f); }
                    *(__half2*)(outp + (size_t)(r0 + 8) * Nfull + colbase + c) = __floats2half2_rn(vx, vy);
                }
            }
        }
    } else {
        __shared__ float spool[8][NB];
        for (int idx = tid; idx < 8 * NB; idx += 256) ((float*)spool)[idx] = 0.f;
        __syncthreads();
        int gmin = g_batch[rowbase];
#pragma unroll
        for (int mi = 0; mi < 2; ++mi) {
            int r0 = rowbase + warp_m * 32 + mi * 16 + grp;
#pragma unroll
            for (int rr = 0; rr < 2; ++rr) {
                int r = r0 + rr * 8;
                if (r >= M) continue;
                int dg = g_batch[r] - gmin;
#pragma unroll
                for (int ni = 0; ni < NI; ++ni) {
                    int c = warp_n * (NB / 2) + ni * 8 + tig * 2;
                    float vx = fmaxf(acc[mi][ni][rr * 2 + 0] + bias[colbase + c], 0.f);
                    float vy = fmaxf(acc[mi][ni][rr * 2 + 1] + bias[colbase + c + 1], 0.f);
                    if (dg < 8) {
                        atomicAdd(&spool[dg][c], vx);
                        atomicAdd(&spool[dg][c + 1], vy);
                    } else {
                        asm volatile("red.global.add.f32 [%0], %1;"
                                     :: "l"(&g_pool[(size_t)(gmin + dg) * 128 + colbase + c]), "f"(vx) : "memory");
                        asm volatile("red.global.add.f32 [%0], %1;"
                                     :: "l"(&g_pool[(size_t)(gmin + dg) * 128 + colbase + c + 1]), "f"(vy) : "memory");
                    }
                }
            }
        }
        __syncthreads();
        int gmax = g_batch[rowbase + valid - 1];
        int span = gmax - gmin + 1; if (span > 8) span = 8;
        for (int idx = tid; idx < span * (NB / 4); idx += 256) {
            int gg = idx >> 4, c4 = (idx & 15) * 4;
            float4 v = *(float4*)&spool[gg][c4];
            float* p = &g_pool[(size_t)(gmin + gg) * 128 + colbase + c4];
            asm volatile("red.global.add.v4.f32 [%0], {%1, %2, %3, %4};"
                         :: "l"(p), "f"(v.x), "f"(v.y), "f"(v.z), "f"(v.w) : "memory");
        }
    }
}

// ---------------- classifier ----------------
__global__ void final_kernel(const float* __restrict__ lw, const float* __restrict__ lb,
                             float* __restrict__ out) {
    int g = blockIdx.x;
    int c = threadIdx.x;  // 16
    float inv = 1.f / fmaxf((float)g_cnt[g], 1.f);
    float acc = lb[c];
#pragma unroll 8
    for (int k = 0; k < 128; ++k)
        acc += g_pool[g * 128 + k] * inv * lw[k * 16 + c];
    out[g * 16 + c] = acc;
}

// ---------------- launch ----------------
extern "C" void kernel_launch(void* const* d_in, const int* in_sizes, int n_in,
                              void* d_out, int out_size) {
    const float* x     = (const float*)d_in[0];
    const void*  ei    = d_in[1];
    const void*  batch = d_in[2];
    int wi = (in_sizes[3] < 100) ? 4 : 3;
    const float* w_stage1 = (const float*)d_in[wi + 0];
    const float* b_stage1 = (const float*)d_in[wi + 1];
    const float* rel1_w   = (const float*)d_in[wi + 2];
    const float* rel1_b   = (const float*)d_in[wi + 3];
    const float* root1_w  = (const float*)d_in[wi + 4];
    const float* rel2_w   = (const float*)d_in[wi + 5];
    const float* rel2_b   = (const float*)d_in[wi + 6];
    const float* root2_w  = (const float*)d_in[wi + 7];
    const float* rel3_w   = (const float*)d_in[wi + 8];
    const float* rel3_b   = (const float*)d_in[wi + 9];
    const float* root3_w  = (const float*)d_in[wi + 10];
    const float* lin_w    = (const float*)d_in[wi + 11];
    const float* lin_b    = (const float*)d_in[wi + 12];
    float* out = (float*)d_out;

    const int M = N_NODES, E = N_EDGES;
    const int MT = (M + 127) / 128;   // 391

    // chunk tiling: 98,98,98,97
    int tiles[NCHUNK], nlo[NCHUNK], nhi[NCHUNK];
    {
        int base = MT / NCHUNK, rem = MT % NCHUNK, t0 = 0;
        for (int c = 0; c < NCHUNK; ++c) {
            tiles[c] = base + (c < rem ? 1 : 0);
            nlo[c] = t0 * 128;
            t0 += tiles[c];
            nhi[c] = t0 * 128 < M ? t0 * 128 : M;
        }
    }

    cudaFuncSetAttribute(gemm_mma_kernel,
                         cudaFuncAttributeMaxDynamicSharedMemorySize, GEMM_SMEM);

    cudaStream_t s2;
    cudaStreamCreateWithFlags(&s2, cudaStreamNonBlocking);
    cudaEvent_t evRoot, evH0, evG[3][NCHUNK], evGemm[3];
    cudaEventCreateWithFlags(&evRoot, cudaEventDisableTiming);
    cudaEventCreateWithFlags(&evH0, cudaEventDisableTiming);
    for (int k = 0; k < 3; ++k) {
        cudaEventCreateWithFlags(&evGemm[k], cudaEventDisableTiming);
        for (int c = 0; c < NCHUNK; ++c)
            cudaEventCreateWithFlags(&evG[k][c], cudaEventDisableTiming);
    }

    cudaEventRecord(evRoot, 0);
    cudaStreamWaitEvent(s2, evRoot, 0);

    // s2: CSR build chain
    zero_deg_kernel<<<(M + 255) / 256, 256, 0, s2>>>();
    convert_edges_hist_kernel<<<(E + 255) / 256, 256, 0, s2>>>(ei, E);
    scan1_kernel<<<NBLK, 1024, 0, s2>>>();
    scan23_kernel<<<NBLK, 1024, 0, s2>>>();
    fill_kernel<<<(E + 255) / 256, 256, 0, s2>>>(E);

    // s0: stage1 GEMM (fp32 x -> fp16 h0) + pool/batch init
    gemm_mma_kernel<<<dim3(MT, 1), 256, GEMM_SMEM>>>(x, -1, w_stage1, nullptr,
                                                     b_stage1, 0, 0, M, 128, 0, 64, 0, 0);
    zero_pool_kernel<<<(NUM_GRAPHS * 128 + 255) / 256, 256>>>();
    convert_batch_count_kernel<<<(M + 255) / 256, 256>>>(batch, M);
    cudaEventRecord(evH0, 0);
    cudaStreamWaitEvent(s2, evH0, 0);  // s2 gathers need h0 (CSR in-order on s2)

    struct LayerCfg {
        int hId, outId;
        const float *rw, *rb, *ww;
        int Ka, Kb, Nfull, pool;
    } L[3] = {
        {0, 1, rel1_w, rel1_b, root1_w, 64, 64, 64, 0},
        {1, 2, rel2_w, rel2_b, root2_w, 64, 64, 128, 0},
        {2, 0, rel3_w, rel3_b, root3_w, 128, 128, 128, 1},
    };

    for (int k = 0; k < 3; ++k) {
        int ycnt = L[k].Nfull / NB;
        int lanes = L[k].Ka / 8;   // 8 or 16
        if (k > 0) cudaStreamWaitEvent(s2, evGemm[k - 1], 0);  // gathers need full prev h
        // serial gathers on s2, per-chunk events
        for (int c = 0; c < NCHUNK; ++c) {
            int nn = nhi[c] - nlo[c];
            int thr = nn * lanes;
            if (lanes == 8)
                gather_kernel<8><<<(thr + 255) / 256, 256, 0, s2>>>(L[k].hId, nlo[c], nhi[c]);
            else
                gather_kernel<16><<<(thr + 255) / 256, 256, 0, s2>>>(L[k].hId, nlo[c], nhi[c]);
            cudaEventRecord(evG[k][c], s2);
        }
        // serial gemms on s0, each waiting its chunk's gather (A = g_agg, device-side)
        for (int c = 0; c < NCHUNK; ++c) {
            cudaStreamWaitEvent(0, evG[k][c], 0);
            gemm_mma_kernel<<<dim3(tiles[c], ycnt), 256, GEMM_SMEM>>>(
                nullptr, L[k].hId, L[k].rw, L[k].ww, L[k].rb, L[k].outId,
                nlo[c], M, L[k].Ka, L[k].Kb, L[k].Nfull, 1, L[k].pool);
        }
        cudaEventRecord(evGemm[k], 0);
    }

    final_kernel<<<NUM_GRAPHS, 16>>>(lin_w, lin_b, out);

    (void)n_in; (void)out_size;
}

// round 15
// speedup vs baseline: 1.0001x; 1.0001x over previous
#include <cuda_runtime.h>
#include <cuda_fp16.h>
#include <cstdint>

#define N_NODES 50000
#define N_EDGES 800000
#define NUM_GRAPHS 512
#define NBLK 49  // ceil(50000/1024)
#define NCHUNK 4

// ---------------- scratch (no allocations allowed) ----------------
__device__ __align__(16) __half g_h0[N_NODES * 64];
__device__ __align__(16) __half g_h1[N_NODES * 64];
__device__ __align__(16) __half g_h2[N_NODES * 128];
__device__ __align__(16) float  g_agg[N_NODES * 128];
__device__ __align__(16) float  g_pool[NUM_GRAPHS * 128];
__device__ int   g_cnt[NUM_GRAPHS];
__device__ int   g_src[N_EDGES];
__device__ int   g_dst[N_EDGES];
__device__ int   g_batch[N_NODES];
__device__ int   g_deg[N_NODES];
__device__ int   g_off[N_NODES + 1];
__device__ int   g_fill[N_NODES];
__device__ int   g_csr[N_EDGES];
__device__ int   g_bsum[NBLK];

__device__ __forceinline__ __half* hbuf_ptr(int id) {
    switch (id) {
        case 0: return g_h0;
        case 1: return g_h1;
        default: return g_h2;
    }
}

// ---------------- converts (dtype-detecting) fused with hist/count ----------------
__global__ void zero_deg_kernel() {
    int i = blockIdx.x * blockDim.x + threadIdx.x;
    if (i < N_NODES) g_deg[i] = 0;
}

__global__ void convert_edges_hist_kernel(const void* __restrict__ ei_raw, int E) {
    const int* w = (const int*)ei_raw;
    bool is64 = true;
#pragma unroll
    for (int j = 1; j < 32; j += 2) is64 &= (w[j] == 0);
    int i = blockIdx.x * blockDim.x + threadIdx.x;
    if (i >= E) return;
    int s, d;
    if (is64) {
        const long long* e64 = (const long long*)ei_raw;
        s = (int)e64[i];
        d = (int)e64[E + i];
    } else {
        s = w[i];
        d = w[E + i];
    }
    g_src[i] = s;
    g_dst[i] = d;
    atomicAdd(&g_deg[d], 1);
}

__global__ void zero_pool_kernel() {
    int i = blockIdx.x * blockDim.x + threadIdx.x;
    if (i < NUM_GRAPHS * 128) g_pool[i] = 0.f;
    if (i < NUM_GRAPHS) g_cnt[i] = 0;
}

__global__ void convert_batch_count_kernel(const void* __restrict__ b_raw, int N) {
    const int* w = (const int*)b_raw;
    bool is64 = true;
#pragma unroll
    for (int j = 0; j < 32; ++j) {
        int idx = N - 32 + j;
        if (idx & 1) is64 &= (w[idx] == 0);
    }
    int i = blockIdx.x * blockDim.x + threadIdx.x;
    if (i >= N) return;
    int b = is64 ? (int)((const long long*)b_raw)[i] : w[i];
    g_batch[i] = b;
    atomicAdd(&g_cnt[b], 1);
}

// ---------------- CSR scan + fill ----------------
__global__ void scan1_kernel() {
    __shared__ int wsum[32];
    int t = threadIdx.x;
    int i = blockIdx.x * 1024 + t;
    int v = (i < N_NODES) ? g_deg[i] : 0;
    int lane = t & 31, wid = t >> 5;
    int x = v;
#pragma unroll
    for (int d = 1; d < 32; d <<= 1) {
        int y = __shfl_up_sync(0xFFFFFFFFu, x, d);
        if (lane >= d) x += y;
    }
    if (lane == 31) wsum[wid] = x;
    __syncthreads();
    if (wid == 0) {
        int w = wsum[lane];
#pragma unroll
        for (int d = 1; d < 32; d <<= 1) {
            int y = __shfl_up_sync(0xFFFFFFFFu, w, d);
            if (lane >= d) w += y;
        }
        wsum[lane] = w;
    }
    __syncthreads();
    int incl = x + ((wid > 0) ? wsum[wid - 1] : 0);
    if (i < N_NODES) g_off[i] = incl - v;
    if (t == 1023) g_bsum[blockIdx.x] = incl;
}

__global__ void scan23_kernel() {
    __shared__ int s[NBLK];
    __shared__ int pre;
    int t = threadIdx.x;
    if (t < NBLK) s[t] = g_bsum[t];
    __syncthreads();
    if (t == 0) {
        int acc = 0;
        for (int j = 0; j < (int)blockIdx.x; ++j) acc += s[j];
        pre = acc;
        if (blockIdx.x == 0) {
            int tot = 0;
            for (int j = 0; j < NBLK; ++j) tot += s[j];
            g_off[N_NODES] = tot;
        }
    }
    __syncthreads();
    int i = blockIdx.x * 1024 + t;
    if (i < N_NODES) {
        int o = g_off[i] + pre;
        g_off[i] = o;
        g_fill[i] = o;
    }
}

__global__ void fill_kernel(int E) {
    int i = blockIdx.x * blockDim.x + threadIdx.x;
    if (i < E) {
        int p = atomicAdd(&g_fill[g_dst[i]], 1);
        g_csr[p] = g_src[i];
    }
}

// ---------------- CSR gather (fp16 h -> fp32 agg) over nodes [n0, n1) ----------------
__device__ __forceinline__ void acc8h(float* acc, uint4 v) {
    const __half2* hp = (const __half2*)&v;
#pragma unroll
    for (int j = 0; j < 4; ++j) {
        float2 f = __half22float2(hp[j]);
        acc[2 * j] += f.x;
        acc[2 * j + 1] += f.y;
    }
}

template <int LANES>   // LANES = dim/8 (8 for 64-dim, 16 for 128-dim)
__global__ void gather_kernel(int hId, int n0, int n1) {
    int gt = blockIdx.x * blockDim.x + threadIdx.x;
    int gid = n0 + gt / LANES;
    int lane = gt & (LANES - 1);
    if (gid >= n1) return;
    const uint4* __restrict__ h = (const uint4*)hbuf_ptr(hId);  // row = LANES uint4
    const int* __restrict__ csr = g_csr;
    int e = g_off[gid], end = g_off[gid + 1];
    float acc[8] = {0.f, 0.f, 0.f, 0.f, 0.f, 0.f, 0.f, 0.f};
    for (; e + 3 < end; e += 4) {
        int s0 = csr[e], s1 = csr[e + 1], s2 = csr[e + 2], s3 = csr[e + 3];
        uint4 v0 = __ldg(&h[(size_t)s0 * LANES + lane]);
        uint4 v1 = __ldg(&h[(size_t)s1 * LANES + lane]);
        uint4 v2 = __ldg(&h[(size_t)s2 * LANES + lane]);
        uint4 v3 = __ldg(&h[(size_t)s3 * LANES + lane]);
        acc8h(acc, v0); acc8h(acc, v1); acc8h(acc, v2); acc8h(acc, v3);
    }
    for (; e < end; ++e) {
        uint4 v0 = __ldg(&h[(size_t)csr[e] * LANES + lane]);
        acc8h(acc, v0);
    }
    float4* ap = (float4*)(g_agg + ((size_t)gid * LANES + lane) * 8);
    ap[0] = make_float4(acc[0], acc[1], acc[2], acc[3]);
    ap[1] = make_float4(acc[4], acc[5], acc[6], acc[7]);
}

// ---------------- tf32 mma.sync GEMM (NB=64 tile, occupancy 3, row-chunked) ----------------
__device__ __forceinline__ float to_tf32(float x) {
    float y;
    asm("cvt.rna.tf32.f32 %0, %1;" : "=f"(y) : "f"(x));
    return y;
}
__device__ __forceinline__ void mma1688(float* d, const uint32_t* a, const uint32_t* b) {
    asm volatile(
        "mma.sync.aligned.m16n8k8.row.col.f32.tf32.tf32.f32 "
        "{%0,%1,%2,%3}, {%4,%5,%6,%7}, {%8,%9}, {%0,%1,%2,%3};\n"
        : "+f"(d[0]), "+f"(d[1]), "+f"(d[2]), "+f"(d[3])
        : "r"(a[0]), "r"(a[1]), "r"(a[2]), "r"(a[3]), "r"(b[0]), "r"(b[1]));
}

#define KC 64
#define LDA 68
#define NB 64
#define NI 4
#define LDB 72
#define GEMM_SMEM ((128 * LDA + KC * LDB) * 4)

// pass0: A = (a32 != nullptr ? a32 : g_agg)  (fp32, K-major).
// pass1 (if Kb>0): A = hbuf[bHalfId] (fp16).
// out: poolMode ? reduce relu into g_pool : store fp16 into hbuf[outId].
__global__ void __launch_bounds__(256, 3)
gemm_mma_kernel(const float* __restrict__ a32, int bHalfId,
                const float* __restrict__ Wa, const float* __restrict__ Wb,
                const float* __restrict__ bias, int outId,
                int rowOff, int M, int Ka, int Kb, int Nfull, int doRelu, int poolMode) {
    extern __shared__ float sm[];
    float* sA = sm;
    float* sB = sm + 128 * LDA;

    int tid = threadIdx.x;
    int wid = tid >> 5, lane = tid & 31;
    int tig = lane & 3, grp = lane >> 2;
    int warp_m = wid & 3, warp_n = wid >> 2;
    int rowbase = rowOff + blockIdx.x * 128;
    int colbase = blockIdx.y * NB;
    int valid = M - rowbase; if (valid > 128) valid = 128;

    const float* A0 = (a32 != nullptr) ? a32 : g_agg;   // device-side symbol!

    float acc[2][NI][4];
#pragma unroll
    for (int mi = 0; mi < 2; ++mi)
#pragma unroll
        for (int ni = 0; ni < NI; ++ni)
#pragma unroll
            for (int j = 0; j < 4; ++j) acc[mi][ni][j] = 0.f;

    const int npass = (Kb > 0) ? 2 : 1;
    for (int pass = 0; pass < npass; ++pass) {
        const float* W = pass ? Wb : Wa;
        const int K = pass ? Kb : Ka;

        for (int kc = 0; kc < K; kc += KC) {
            __syncthreads();
            if (pass == 0) {
                for (int idx = tid; idx < 128 * 16; idx += 256) {
                    int r = idx >> 4, k4 = (idx & 15) * 4;
                    float4 v = make_float4(0.f, 0.f, 0.f, 0.f);
                    if (r < valid)
                        v = *(const float4*)(A0 + (size_t)(rowbase + r) * K + kc + k4);
                    float* p = sA + r * LDA + k4;
                    p[0] = to_tf32(v.x); p[1] = to_tf32(v.y);
                    p[2] = to_tf32(v.z); p[3] = to_tf32(v.w);
                }
            } else {
                const __half* H = hbuf_ptr(bHalfId);
                for (int idx = tid; idx < 128 * 8; idx += 256) {
                    int r = idx >> 3, k8 = (idx & 7) * 8;
                    uint4 v = make_uint4(0, 0, 0, 0);
                    if (r < valid)
                        v = *(const uint4*)(H + (size_t)(rowbase + r) * K + kc + k8);
                    const __half2* hp = (const __half2*)&v;
                    float* p = sA + r * LDA + k8;
#pragma unroll
                    for (int j = 0; j < 4; ++j) {
                        float2 f = __half22float2(hp[j]);
                        p[2 * j] = f.x;         // fp16 -> tf32 is exact
                        p[2 * j + 1] = f.y;
                    }
                }
            }
            for (int idx = tid; idx < KC * (NB / 4); idx += 256) {
                int r = idx >> 4, c4 = (idx & 15) * 4;
                float4 v = *(const float4*)(W + (size_t)(kc + r) * Nfull + colbase + c4);
                float* p = sB + r * LDB + c4;
                p[0] = to_tf32(v.x); p[1] = to_tf32(v.y);
                p[2] = to_tf32(v.z); p[3] = to_tf32(v.w);
            }
            __syncthreads();

#pragma unroll
            for (int k8 = 0; k8 < KC / 8; ++k8) {
                int k0 = k8 * 8;
                uint32_t afr[2][4];
#pragma unroll
                for (int mi = 0; mi < 2; ++mi) {
                    int r0 = warp_m * 32 + mi * 16 + grp;
                    afr[mi][0] = __float_as_uint(sA[r0 * LDA + k0 + tig]);
                    afr[mi][1] = __float_as_uint(sA[(r0 + 8) * LDA + k0 + tig]);
                    afr[mi][2] = __float_as_uint(sA[r0 * LDA + k0 + tig + 4]);
                    afr[mi][3] = __float_as_uint(sA[(r0 + 8) * LDA + k0 + tig + 4]);
                }
                uint32_t bfr[NI][2];
#pragma unroll
                for (int ni = 0; ni < NI; ++ni) {
                    int c = warp_n * (NB / 2) + ni * 8 + grp;
                    bfr[ni][0] = __float_as_uint(sB[(k0 + tig) * LDB + c]);
                    bfr[ni][1] = __float_as_uint(sB[(k0 + tig + 4) * LDB + c]);
                }
#pragma unroll
                for (int mi = 0; mi < 2; ++mi)
#pragma unroll
                    for (int ni = 0; ni < NI; ++ni)
                        mma1688(acc[mi][ni], afr[mi], bfr[ni]);
            }
        }
    }

    if (!poolMode) {
        __half* outp = hbuf_ptr(outId);
#pragma unroll
        for (int mi = 0; mi < 2; ++mi) {
            int r0 = rowbase + warp_m * 32 + mi * 16 + grp;
#pragma unroll
            for (int ni = 0; ni < NI; ++ni) {
                int c = warp_n * (NB / 2) + ni * 8 + tig * 2;
                float b0 = bias[colbase + c], b1 = bias[colbase + c + 1];
                if (r0 < M) {
                    float vx = acc[mi][ni][0] + b0, vy = acc[mi][ni][1] + b1;
                    if (doRelu) { vx = fmaxf(vx, 0.f); vy = fmaxf(vy, 0.f); }
                    *(__half2*)(outp + (size_t)r0 * Nfull + colbase + c) = __floats2half2_rn(vx, vy);
                }
                if (r0 + 8 < M) {
                    float vx = acc[mi][ni][2] + b0, vy = acc[mi][ni][3] + b1;
                    if (doRelu) { vx = fmaxf(vx, 0.f); vy = fmaxf(vy, 0.f); }
                    *(__half2*)(outp + (size_t)(r0 + 8) * Nfull + colbase + c) = __floats2half2_rn(vx, vy);
                }
            }
        }
    } else {
        __shared__ float spool[8][NB];
        for (int idx = tid; idx < 8 * NB; idx += 256) ((float*)spool)[idx] = 0.f;
        __syncthreads();
        int gmin = g_batch[rowbase];
#pragma unroll
        for (int mi = 0; mi < 2; ++mi) {
            int r0 = rowbase + warp_m * 32 + mi * 16 + grp;
#pragma unroll
            for (int rr = 0; rr < 2; ++rr) {
                int r = r0 + rr * 8;
                if (r >= M) continue;
                int dg = g_batch[r] - gmin;
#pragma unroll
                for (int ni = 0; ni < NI; ++ni) {
                    int c = warp_n * (NB / 2) + ni * 8 + tig * 2;
                    float vx = fmaxf(acc[mi][ni][rr * 2 + 0] + bias[colbase + c], 0.f);
                    float vy = fmaxf(acc[mi][ni][rr * 2 + 1] + bias[colbase + c + 1], 0.f);
                    if (dg < 8) {
                        atomicAdd(&spool[dg][c], vx);
                        atomicAdd(&spool[dg][c + 1], vy);
                    } else {
                        asm volatile("red.global.add.f32 [%0], %1;"
                                     :: "l"(&g_pool[(size_t)(gmin + dg) * 128 + colbase + c]), "f"(vx) : "memory");
                        asm volatile("red.global.add.f32 [%0], %1;"
                                     :: "l"(&g_pool[(size_t)(gmin + dg) * 128 + colbase + c + 1]), "f"(vy) : "memory");
                    }
                }
            }
        }
        __syncthreads();
        int gmax = g_batch[rowbase + valid - 1];
        int span = gmax - gmin + 1; if (span > 8) span = 8;
        for (int idx = tid; idx < span * (NB / 4); idx += 256) {
            int gg = idx >> 4, c4 = (idx & 15) * 4;
            float4 v = *(float4*)&spool[gg][c4];
            float* p = &g_pool[(size_t)(gmin + gg) * 128 + colbase + c4];
            asm volatile("red.global.add.v4.f32 [%0], {%1, %2, %3, %4};"
                         :: "l"(p), "f"(v.x), "f"(v.y), "f"(v.z), "f"(v.w) : "memory");
        }
    }
}

// ---------------- classifier ----------------
__global__ void final_kernel(const float* __restrict__ lw, const float* __restrict__ lb,
                             float* __restrict__ out) {
    int g = blockIdx.x;
    int c = threadIdx.x;  // 16
    float inv = 1.f / fmaxf((float)g_cnt[g], 1.f);
    float acc = lb[c];
#pragma unroll 8
    for (int k = 0; k < 128; ++k)
        acc += g_pool[g * 128 + k] * inv * lw[k * 16 + c];
    out[g * 16 + c] = acc;
}

// ---------------- launch ----------------
extern "C" void kernel_launch(void* const* d_in, const int* in_sizes, int n_in,
                              void* d_out, int out_size) {
    const float* x     = (const float*)d_in[0];
    const void*  ei    = d_in[1];
    const void*  batch = d_in[2];
    int wi = (in_sizes[3] < 100) ? 4 : 3;
    const float* w_stage1 = (const float*)d_in[wi + 0];
    const float* b_stage1 = (const float*)d_in[wi + 1];
    const float* rel1_w   = (const float*)d_in[wi + 2];
    const float* rel1_b   = (const float*)d_in[wi + 3];
    const float* root1_w  = (const float*)d_in[wi + 4];
    const float* rel2_w   = (const float*)d_in[wi + 5];
    const float* rel2_b   = (const float*)d_in[wi + 6];
    const float* root2_w  = (const float*)d_in[wi + 7];
    const float* rel3_w   = (const float*)d_in[wi + 8];
    const float* rel3_b   = (const float*)d_in[wi + 9];
    const float* root3_w  = (const float*)d_in[wi + 10];
    const float* lin_w    = (const float*)d_in[wi + 11];
    const float* lin_b    = (const float*)d_in[wi + 12];
    float* out = (float*)d_out;

    const int M = N_NODES, E = N_EDGES;
    const int MT = (M + 127) / 128;   // 391

    // chunk tiling: 98,98,98,97
    int tiles[NCHUNK], nlo[NCHUNK], nhi[NCHUNK];
    {
        int base = MT / NCHUNK, rem = MT % NCHUNK, t0 = 0;
        for (int c = 0; c < NCHUNK; ++c) {
            tiles[c] = base + (c < rem ? 1 : 0);
            nlo[c] = t0 * 128;
            t0 += tiles[c];
            nhi[c] = t0 * 128 < M ? t0 * 128 : M;
        }
    }

    cudaFuncSetAttribute(gemm_mma_kernel,
                         cudaFuncAttributeMaxDynamicSharedMemorySize, GEMM_SMEM);

    cudaStream_t s2;
    cudaStreamCreateWithFlags(&s2, cudaStreamNonBlocking);
    cudaEvent_t evRoot, evH0, evG[3][NCHUNK], evGemm[3];
    cudaEventCreateWithFlags(&evRoot, cudaEventDisableTiming);
    cudaEventCreateWithFlags(&evH0, cudaEventDisableTiming);
    for (int k = 0; k < 3; ++k) {
        cudaEventCreateWithFlags(&evGemm[k], cudaEventDisableTiming);
        for (int c = 0; c < NCHUNK; ++c)
            cudaEventCreateWithFlags(&evG[k][c], cudaEventDisableTiming);
    }

    cudaEventRecord(evRoot, 0);
    cudaStreamWaitEvent(s2, evRoot, 0);

    // s2: CSR build chain
    zero_deg_kernel<<<(M + 255) / 256, 256, 0, s2>>>();
    convert_edges_hist_kernel<<<(E + 255) / 256, 256, 0, s2>>>(ei, E);
    scan1_kernel<<<NBLK, 1024, 0, s2>>>();
    scan23_kernel<<<NBLK, 1024, 0, s2>>>();
    fill_kernel<<<(E + 255) / 256, 256, 0, s2>>>(E);

    // s0: stage1 GEMM (fp32 x -> fp16 h0) + pool/batch init
    gemm_mma_kernel<<<dim3(MT, 1), 256, GEMM_SMEM>>>(x, -1, w_stage1, nullptr,
                                                     b_stage1, 0, 0, M, 128, 0, 64, 0, 0);
    zero_pool_kernel<<<(NUM_GRAPHS * 128 + 255) / 256, 256>>>();
    convert_batch_count_kernel<<<(M + 255) / 256, 256>>>(batch, M);
    cudaEventRecord(evH0, 0);
    cudaStreamWaitEvent(s2, evH0, 0);  // s2 gathers need h0 (CSR in-order on s2)

    struct LayerCfg {
        int hId, outId;
        const float *rw, *rb, *ww;
        int Ka, Kb, Nfull, pool;
    } L[3] = {
        {0, 1, rel1_w, rel1_b, root1_w, 64, 64, 64, 0},
        {1, 2, rel2_w, rel2_b, root2_w, 64, 64, 128, 0},
        {2, 0, rel3_w, rel3_b, root3_w, 128, 128, 128, 1},
    };

    for (int k = 0; k < 3; ++k) {
        int ycnt = L[k].Nfull / NB;
        int lanes = L[k].Ka / 8;   // 8 or 16
        if (k > 0) cudaStreamWaitEvent(s2, evGemm[k - 1], 0);  // gathers need full prev h
        // serial gathers on s2, per-chunk events
        for (int c = 0; c < NCHUNK; ++c) {
            int nn = nhi[c] - nlo[c];
            int thr = nn * lanes;
            if (lanes == 8)
                gather_kernel<8><<<(thr + 255) / 256, 256, 0, s2>>>(L[k].hId, nlo[c], nhi[c]);
            else
                gather_kernel<16><<<(thr + 255) / 256, 256, 0, s2>>>(L[k].hId, nlo[c], nhi[c]);
            cudaEventRecord(evG[k][c], s2);
        }
        // serial gemms on s0, each waiting its chunk's gather (A = g_agg, device-side)
        for (int c = 0; c < NCHUNK; ++c) {
            cudaStreamWaitEvent(0, evG[k][c], 0);
            gemm_mma_kernel<<<dim3(tiles[c], ycnt), 256, GEMM_SMEM>>>(
                nullptr, L[k].hId, L[k].rw, L[k].ww, L[k].rb, L[k].outId,
                nlo[c], M, L[k].Ka, L[k].Kb, L[k].Nfull, 1, L[k].pool);
        }
        cudaEventRecord(evGemm[k], 0);
    }

    final_kernel<<<NUM_GRAPHS, 16>>>(lin_w, lin_b, out);

    (void)n_in; (void)out_size;
}

// round 16
// speedup vs baseline: 1.5366x; 1.5364x over previous
#include <cuda_runtime.h>
#include <cuda_fp16.h>
#include <cstdint>

#define N_NODES 50000
#define N_EDGES 800000
#define NUM_GRAPHS 512
#define NBLK 49  // ceil(50000/1024)

#define CH0_TILES 196
#define CH0_NODES (CH0_TILES * 128)   // 25088

// ---------------- scratch (no allocations allowed) ----------------
__device__ __align__(16) __half g_h0[N_NODES * 64];
__device__ __align__(16) __half g_h1[N_NODES * 64];
__device__ __align__(16) __half g_h2[N_NODES * 128];
__device__ __align__(16) float  g_agg[N_NODES * 128];
__device__ __align__(16) float  g_pool[NUM_GRAPHS * 128];
__device__ int   g_cnt[NUM_GRAPHS];
__device__ int   g_src[N_EDGES];
__device__ int   g_dst[N_EDGES];
__device__ int   g_batch[N_NODES];
__device__ int   g_deg[N_NODES];
__device__ int   g_off[N_NODES + 1];
__device__ int   g_fill[N_NODES];
__device__ int   g_csr[N_EDGES];
__device__ int   g_bsum[NBLK];

__device__ __forceinline__ __half* hbuf_ptr(int id) {
    switch (id) {
        case 0: return g_h0;
        case 1: return g_h1;
        default: return g_h2;
    }
}

// ---------------- converts (dtype-detecting) fused with hist/count ----------------
__global__ void zero_deg_kernel() {
    int i = blockIdx.x * blockDim.x + threadIdx.x;
    if (i < N_NODES) g_deg[i] = 0;
}

__global__ void convert_edges_hist_kernel(const void* __restrict__ ei_raw, int E) {
    const int* w = (const int*)ei_raw;
    bool is64 = true;
#pragma unroll
    for (int j = 1; j < 32; j += 2) is64 &= (w[j] == 0);
    int i = blockIdx.x * blockDim.x + threadIdx.x;
    if (i >= E) return;
    int s, d;
    if (is64) {
        const long long* e64 = (const long long*)ei_raw;
        s = (int)e64[i];
        d = (int)e64[E + i];
    } else {
        s = w[i];
        d = w[E + i];
    }
    g_src[i] = s;
    g_dst[i] = d;
    atomicAdd(&g_deg[d], 1);
}

__global__ void zero_pool_kernel() {
    int i = blockIdx.x * blockDim.x + threadIdx.x;
    if (i < NUM_GRAPHS * 128) g_pool[i] = 0.f;
    if (i < NUM_GRAPHS) g_cnt[i] = 0;
}

__global__ void convert_batch_count_kernel(const void* __restrict__ b_raw, int N) {
    const int* w = (const int*)b_raw;
    bool is64 = true;
#pragma unroll
    for (int j = 0; j < 32; ++j) {
        int idx = N - 32 + j;
        if (idx & 1) is64 &= (w[idx] == 0);
    }
    int i = blockIdx.x * blockDim.x + threadIdx.x;
    if (i >= N) return;
    int b = is64 ? (int)((const long long*)b_raw)[i] : w[i];
    g_batch[i] = b;
    atomicAdd(&g_cnt[b], 1);
}

// ---------------- CSR scan + fill ----------------
__global__ void scan1_kernel() {
    __shared__ int wsum[32];
    int t = threadIdx.x;
    int i = blockIdx.x * 1024 + t;
    int v = (i < N_NODES) ? g_deg[i] : 0;
    int lane = t & 31, wid = t >> 5;
    int x = v;
#pragma unroll
    for (int d = 1; d < 32; d <<= 1) {
        int y = __shfl_up_sync(0xFFFFFFFFu, x, d);
        if (lane >= d) x += y;
    }
    if (lane == 31) wsum[wid] = x;
    __syncthreads();
    if (wid == 0) {
        int w = wsum[lane];
#pragma unroll
        for (int d = 1; d < 32; d <<= 1) {
            int y = __shfl_up_sync(0xFFFFFFFFu, w, d);
            if (lane >= d) w += y;
        }
        wsum[lane] = w;
    }
    __syncthreads();
    int incl = x + ((wid > 0) ? wsum[wid - 1] : 0);
    if (i < N_NODES) g_off[i] = incl - v;
    if (t == 1023) g_bsum[blockIdx.x] = incl;
}

__global__ void scan23_kernel() {
    __shared__ int s[NBLK];
    __shared__ int pre;
    int t = threadIdx.x;
    if (t < NBLK) s[t] = g_bsum[t];
    __syncthreads();
    if (t == 0) {
        int acc = 0;
        for (int j = 0; j < (int)blockIdx.x; ++j) acc += s[j];
        pre = acc;
        if (blockIdx.x == 0) {
            int tot = 0;
            for (int j = 0; j < NBLK; ++j) tot += s[j];
            g_off[N_NODES] = tot;
        }
    }
    __syncthreads();
    int i = blockIdx.x * 1024 + t;
    if (i < N_NODES) {
        int o = g_off[i] + pre;
        g_off[i] = o;
        g_fill[i] = o;
    }
}

__global__ void fill_kernel(int E) {
    int i = blockIdx.x * blockDim.x + threadIdx.x;
    if (i < E) {
        int p = atomicAdd(&g_fill[g_dst[i]], 1);
        g_csr[p] = g_src[i];
    }
}

// ---------------- CSR gather (fp16 h -> fp32 agg) over nodes [n0, n1) ----------------
__device__ __forceinline__ void acc8h(float* acc, uint4 v) {
    const __half2* hp = (const __half2*)&v;
#pragma unroll
    for (int j = 0; j < 4; ++j) {
        float2 f = __half22float2(hp[j]);
        acc[2 * j] += f.x;
        acc[2 * j + 1] += f.y;
    }
}

template <int LANES>   // LANES = dim/8 (8 for 64-dim, 16 for 128-dim)
__global__ void gather_kernel(int hId, int n0, int n1) {
    int gt = blockIdx.x * blockDim.x + threadIdx.x;
    int gid = n0 + gt / LANES;
    int lane = gt & (LANES - 1);
    if (gid >= n1) return;
    const uint4* __restrict__ h = (const uint4*)hbuf_ptr(hId);  // row = LANES uint4
    const int* __restrict__ csr = g_csr;
    int e = g_off[gid], end = g_off[gid + 1];
    float acc[8] = {0.f, 0.f, 0.f, 0.f, 0.f, 0.f, 0.f, 0.f};
    for (; e + 3 < end; e += 4) {
        int s0 = csr[e], s1 = csr[e + 1], s2 = csr[e + 2], s3 = csr[e + 3];
        uint4 v0 = __ldg(&h[(size_t)s0 * LANES + lane]);
        uint4 v1 = __ldg(&h[(size_t)s1 * LANES + lane]);
        uint4 v2 = __ldg(&h[(size_t)s2 * LANES + lane]);
        uint4 v3 = __ldg(&h[(size_t)s3 * LANES + lane]);
        acc8h(acc, v0); acc8h(acc, v1); acc8h(acc, v2); acc8h(acc, v3);
    }
    for (; e < end; ++e) {
        uint4 v0 = __ldg(&h[(size_t)csr[e] * LANES + lane]);
        acc8h(acc, v0);
    }
    float4* ap = (float4*)(g_agg + ((size_t)gid * LANES + lane) * 8);
    ap[0] = make_float4(acc[0], acc[1], acc[2], acc[3]);
    ap[1] = make_float4(acc[4], acc[5], acc[6], acc[7]);
}

// ---------------- tf32 mma.sync GEMM (NB=64 tile, occupancy 3, row-chunked) ----------------
__device__ __forceinline__ float to_tf32(float x) {
    float y;
    asm("cvt.rna.tf32.f32 %0, %1;" : "=f"(y) : "f"(x));
    return y;
}
__device__ __forceinline__ void mma1688(float* d, const uint32_t* a, const uint32_t* b) {
    asm volatile(
        "mma.sync.aligned.m16n8k8.row.col.f32.tf32.tf32.f32 "
        "{%0,%1,%2,%3}, {%4,%5,%6,%7}, {%8,%9}, {%0,%1,%2,%3};\n"
        : "+f"(d[0]), "+f"(d[1]), "+f"(d[2]), "+f"(d[3])
        : "r"(a[0]), "r"(a[1]), "r"(a[2]), "r"(a[3]), "r"(b[0]), "r"(b[1]));
}

#define KC 64
#define LDA 68
#define NB 64
#define NI 4
#define LDB 72
#define GEMM_SMEM ((128 * LDA + KC * LDB) * 4)

// pass0: A = (a32 != nullptr ? a32 : g_agg)  (fp32, K-major).
// pass1 (if Kb>0): A = hbuf[bHalfId] (fp16).
// out: poolMode ? reduce relu into g_pool : store fp16 into hbuf[outId].
__global__ void __launch_bounds__(256, 3)
gemm_mma_kernel(const float* __restrict__ a32, int bHalfId,
                const float* __restrict__ Wa, const float* __restrict__ Wb,
                const float* __restrict__ bias, int outId,
                int rowOff, int M, int Ka, int Kb, int Nfull, int doRelu, int poolMode) {
    extern __shared__ float sm[];
    float* sA = sm;
    float* sB = sm + 128 * LDA;

    int tid = threadIdx.x;
    int wid = tid >> 5, lane = tid & 31;
    int tig = lane & 3, grp = lane >> 2;
    int warp_m = wid & 3, warp_n = wid >> 2;
    int rowbase = rowOff + blockIdx.x * 128;
    int colbase = blockIdx.y * NB;
    int valid = M - rowbase; if (valid > 128) valid = 128;

    const float* A0 = (a32 != nullptr) ? a32 : g_agg;   // device-side symbol

    float acc[2][NI][4];
#pragma unroll
    for (int mi = 0; mi < 2; ++mi)
#pragma unroll
        for (int ni = 0; ni < NI; ++ni)
#pragma unroll
            for (int j = 0; j < 4; ++j) acc[mi][ni][j] = 0.f;

    const int npass = (Kb > 0) ? 2 : 1;
    for (int pass = 0; pass < npass; ++pass) {
        const float* W = pass ? Wb : Wa;
        const int K = pass ? Kb : Ka;

        for (int kc = 0; kc < K; kc += KC) {
            __syncthreads();
            if (pass == 0) {
                for (int idx = tid; idx < 128 * 16; idx += 256) {
                    int r = idx >> 4, k4 = (idx & 15) * 4;
                    float4 v = make_float4(0.f, 0.f, 0.f, 0.f);
                    if (r < valid)
                        v = *(const float4*)(A0 + (size_t)(rowbase + r) * K + kc + k4);
                    float* p = sA + r * LDA + k4;
                    p[0] = to_tf32(v.x); p[1] = to_tf32(v.y);
                    p[2] = to_tf32(v.z); p[3] = to_tf32(v.w);
                }
            } else {
                const __half* H = hbuf_ptr(bHalfId);
                for (int idx = tid; idx < 128 * 8; idx += 256) {
                    int r = idx >> 3, k8 = (idx & 7) * 8;
                    uint4 v = make_uint4(0, 0, 0, 0);
                    if (r < valid)
                        v = *(const uint4*)(H + (size_t)(rowbase + r) * K + kc + k8);
                    const __half2* hp = (const __half2*)&v;
                    float* p = sA + r * LDA + k8;
#pragma unroll
                    for (int j = 0; j < 4; ++j) {
                        float2 f = __half22float2(hp[j]);
                        p[2 * j] = f.x;         // fp16 -> tf32 is exact
                        p[2 * j + 1] = f.y;
                    }
                }
            }
            for (int idx = tid; idx < KC * (NB / 4); idx += 256) {
                int r = idx >> 4, c4 = (idx & 15) * 4;
                float4 v = *(const float4*)(W + (size_t)(kc + r) * Nfull + colbase + c4);
                float* p = sB + r * LDB + c4;
                p[0] = to_tf32(v.x); p[1] = to_tf32(v.y);
                p[2] = to_tf32(v.z); p[3] = to_tf32(v.w);
            }
            __syncthreads();

#pragma unroll
            for (int k8 = 0; k8 < KC / 8; ++k8) {
                int k0 = k8 * 8;
                uint32_t afr[2][4];
#pragma unroll
                for (int mi = 0; mi < 2; ++mi) {
                    int r0 = warp_m * 32 + mi * 16 + grp;
                    afr[mi][0] = __float_as_uint(sA[r0 * LDA + k0 + tig]);
                    afr[mi][1] = __float_as_uint(sA[(r0 + 8) * LDA + k0 + tig]);
                    afr[mi][2] = __float_as_uint(sA[r0 * LDA + k0 + tig + 4]);
                    afr[mi][3] = __float_as_uint(sA[(r0 + 8) * LDA + k0 + tig + 4]);
                }
                uint32_t bfr[NI][2];
#pragma unroll
                for (int ni = 0; ni < NI; ++ni) {
                    int c = warp_n * (NB / 2) + ni * 8 + grp;
                    bfr[ni][0] = __float_as_uint(sB[(k0 + tig) * LDB + c]);
                    bfr[ni][1] = __float_as_uint(sB[(k0 + tig + 4) * LDB + c]);
                }
#pragma unroll
                for (int mi = 0; mi < 2; ++mi)
#pragma unroll
                    for (int ni = 0; ni < NI; ++ni)
                        mma1688(acc[mi][ni], afr[mi], bfr[ni]);
            }
        }
    }

    if (!poolMode) {
        __half* outp = hbuf_ptr(outId);
#pragma unroll
        for (int mi = 0; mi < 2; ++mi) {
            int r0 = rowbase + warp_m * 32 + mi * 16 + grp;
#pragma unroll
            for (int ni = 0; ni < NI; ++ni) {
                int c = warp_n * (NB / 2) + ni * 8 + tig * 2;
                float b0 = bias[colbase + c], b1 = bias[colbase + c + 1];
                if (r0 < M) {
                    float vx = acc[mi][ni][0] + b0, vy = acc[mi][ni][1] + b1;
                    if (doRelu) { vx = fmaxf(vx, 0.f); vy = fmaxf(vy, 0.f); }
                    *(__half2*)(outp + (size_t)r0 * Nfull + colbase + c) = __floats2half2_rn(vx, vy);
                }
                if (r0 + 8 < M) {
                    float vx = acc[mi][ni][2] + b0, vy = acc[mi][ni][3] + b1;
                    if (doRelu) { vx = fmaxf(vx, 0.f); vy = fmaxf(vy, 0.f); }
                    *(__half2*)(outp + (size_t)(r0 + 8) * Nfull + colbase + c) = __floats2half2_rn(vx, vy);
                }
            }
        }
    } else {
        __shared__ float spool[8][NB];
        for (int idx = tid; idx < 8 * NB; idx += 256) ((float*)spool)[idx] = 0.f;
        __syncthreads();
        int gmin = g_batch[rowbase];
#pragma unroll
        for (int mi = 0; mi < 2; ++mi) {
            int r0 = rowbase + warp_m * 32 + mi * 16 + grp;
#pragma unroll
            for (int rr = 0; rr < 2; ++rr) {
                int r = r0 + rr * 8;
                if (r >= M) continue;
                int dg = g_batch[r] - gmin;
#pragma unroll
                for (int ni = 0; ni < NI; ++ni) {
                    int c = warp_n * (NB / 2) + ni * 8 + tig * 2;
                    float vx = fmaxf(acc[mi][ni][rr * 2 + 0] + bias[colbase + c], 0.f);
                    float vy = fmaxf(acc[mi][ni][rr * 2 + 1] + bias[colbase + c + 1], 0.f);
                    if (dg < 8) {
                        atomicAdd(&spool[dg][c], vx);
                        atomicAdd(&spool[dg][c + 1], vy);
                    } else {
                        asm volatile("red.global.add.f32 [%0], %1;"
                                     :: "l"(&g_pool[(size_t)(gmin + dg) * 128 + colbase + c]), "f"(vx) : "memory");
                        asm volatile("red.global.add.f32 [%0], %1;"
                                     :: "l"(&g_pool[(size_t)(gmin + dg) * 128 + colbase + c + 1]), "f"(vy) : "memory");
                    }
                }
            }
        }
        __syncthreads();
        int gmax = g_batch[rowbase + valid - 1];
        int span = gmax - gmin + 1; if (span > 8) span = 8;
        for (int idx = tid; idx < span * (NB / 4); idx += 256) {
            int gg = idx >> 4, c4 = (idx & 15) * 4;
            float4 v = *(float4*)&spool[gg][c4];
            float* p = &g_pool[(size_t)(gmin + gg) * 128 + colbase + c4];
            asm volatile("red.global.add.v4.f32 [%0], {%1, %2, %3, %4};"
                         :: "l"(p), "f"(v.x), "f"(v.y), "f"(v.z), "f"(v.w) : "memory");
        }
    }
}

// ---------------- classifier ----------------
__global__ void final_kernel(const float* __restrict__ lw, const float* __restrict__ lb,
                             float* __restrict__ out) {
    int g = blockIdx.x;
    int c = threadIdx.x;  // 16
    float inv = 1.f / fmaxf((float)g_cnt[g], 1.f);
    float acc = lb[c];
#pragma unroll 8
    for (int k = 0; k < 128; ++k)
        acc += g_pool[g * 128 + k] * inv * lw[k * 16 + c];
    out[g * 16 + c] = acc;
}

// ---------------- launch ----------------
extern "C" void kernel_launch(void* const* d_in, const int* in_sizes, int n_in,
                              void* d_out, int out_size) {
    const float* x     = (const float*)d_in[0];
    const void*  ei    = d_in[1];
    const void*  batch = d_in[2];
    int wi = (in_sizes[3] < 100) ? 4 : 3;
    const float* w_stage1 = (const float*)d_in[wi + 0];
    const float* b_stage1 = (const float*)d_in[wi + 1];
    const float* rel1_w   = (const float*)d_in[wi + 2];
    const float* rel1_b   = (const float*)d_in[wi + 3];
    const float* root1_w  = (const float*)d_in[wi + 4];
    const float* rel2_w   = (const float*)d_in[wi + 5];
    const float* rel2_b   = (const float*)d_in[wi + 6];
    const float* root2_w  = (const float*)d_in[wi + 7];
    const float* rel3_w   = (const float*)d_in[wi + 8];
    const float* rel3_b   = (const float*)d_in[wi + 9];
    const float* root3_w  = (const float*)d_in[wi + 10];
    const float* lin_w    = (const float*)d_in[wi + 11];
    const float* lin_b    = (const float*)d_in[wi + 12];
    float* out = (float*)d_out;

    const int M = N_NODES, E = N_EDGES;
    const int MT = (M + 127) / 128;           // 391
    const int T0 = CH0_TILES;                 // 196
    const int T1 = MT - CH0_TILES;            // 195
    const int N0 = CH0_NODES;                 // 25088

    cudaFuncSetAttribute(gemm_mma_kernel,
                         cudaFuncAttributeMaxDynamicSharedMemorySize, GEMM_SMEM);

    cudaStream_t s2;
    cudaStreamCreateWithFlags(&s2, cudaStreamNonBlocking);
    cudaEvent_t evRoot, evCsr, evH0, evL[3][2];
    cudaEventCreateWithFlags(&evRoot, cudaEventDisableTiming);
    cudaEventCreateWithFlags(&evCsr, cudaEventDisableTiming);
    cudaEventCreateWithFlags(&evH0, cudaEventDisableTiming);
    for (int k = 0; k < 3; ++k)
        for (int c = 0; c < 2; ++c)
            cudaEventCreateWithFlags(&evL[k][c], cudaEventDisableTiming);

    cudaEventRecord(evRoot, 0);
    cudaStreamWaitEvent(s2, evRoot, 0);

    // s2: CSR build chain
    zero_deg_kernel<<<(M + 255) / 256, 256, 0, s2>>>();
    convert_edges_hist_kernel<<<(E + 255) / 256, 256, 0, s2>>>(ei, E);
    scan1_kernel<<<NBLK, 1024, 0, s2>>>();
    scan23_kernel<<<NBLK, 1024, 0, s2>>>();
    fill_kernel<<<(E + 255) / 256, 256, 0, s2>>>(E);
    cudaEventRecord(evCsr, s2);

    // s0: stage1 GEMM (fp32 x -> fp16 h0) + pool/batch init (independent of CSR)
    gemm_mma_kernel<<<dim3(MT, 1), 256, GEMM_SMEM>>>(x, -1, w_stage1, nullptr,
                                                     b_stage1, 0, 0, M, 128, 0, 64, 0, 0);
    zero_pool_kernel<<<(NUM_GRAPHS * 128 + 255) / 256, 256>>>();
    convert_batch_count_kernel<<<(M + 255) / 256, 256>>>(batch, M);
    cudaEventRecord(evH0, 0);

    // joins: s0 needs CSR; s2 needs h0/pool/batch
    cudaStreamWaitEvent(0, evCsr, 0);
    cudaStreamWaitEvent(s2, evH0, 0);

    struct LayerCfg {
        int hId, outId;
        const float *rw, *rb, *ww;
        int Ka, Kb, Nfull, pool;
    } L[3] = {
        {0, 1, rel1_w, rel1_b, root1_w, 64, 64, 64, 0},
        {1, 2, rel2_w, rel2_b, root2_w, 64, 64, 128, 0},
        {2, 0, rel3_w, rel3_b, root3_w, 128, 128, 128, 1},
    };

    for (int k = 0; k < 3; ++k) {
        int lanes = L[k].Ka / 8;   // 8 or 16
        int ycnt = L[k].Nfull / NB;
        // chunk 0 on s0, chunk 1 on s2 — gathers run CONCURRENTLY (full TLP),
        // each stream's gemm follows its own gather in program order.
        if (lanes == 8) {
            gather_kernel<8><<<(N0 * 8 + 255) / 256, 256>>>(L[k].hId, 0, N0);
            gather_kernel<8><<<((M - N0) * 8 + 255) / 256, 256, 0, s2>>>(L[k].hId, N0, M);
        } else {
            gather_kernel<16><<<(N0 * 16 + 255) / 256, 256>>>(L[k].hId, 0, N0);
            gather_kernel<16><<<((M - N0) * 16 + 255) / 256, 256, 0, s2>>>(L[k].hId, N0, M);
        }
        gemm_mma_kernel<<<dim3(T0, ycnt), 256, GEMM_SMEM>>>(
            nullptr, L[k].hId, L[k].rw, L[k].ww, L[k].rb, L[k].outId,
            0, M, L[k].Ka, L[k].Kb, L[k].Nfull, 1, L[k].pool);
        gemm_mma_kernel<<<dim3(T1, ycnt), 256, GEMM_SMEM, s2>>>(
            nullptr, L[k].hId, L[k].rw, L[k].ww, L[k].rb, L[k].outId,
            N0, M, L[k].Ka, L[k].Kb, L[k].Nfull, 1, L[k].pool);
        // cross-join: next layer's gathers read full h
        cudaEventRecord(evL[k][0], 0);
        cudaEventRecord(evL[k][1], s2);
        cudaStreamWaitEvent(0, evL[k][1], 0);
        cudaStreamWaitEvent(s2, evL[k][0], 0);
    }

    final_kernel<<<NUM_GRAPHS, 16>>>(lin_w, lin_b, out);

    (void)n_in; (void)out_size;
}